// round 14
// baseline (speedup 1.0000x reference)
#include <cuda_runtime.h>
#include <cuda_bf16.h>
#include <stdint.h>
#include <math.h>

#define FD 128
#define RD 64
#define NMAX 8192
#define LMAX 5

// ---------------- scratch (no runtime allocation allowed) ----------------
__device__ float g_S [NMAX*RD];
// pre-transposed/split weight images: B[n][k] packed as uint32 (2 bf16 along k)
__device__ uint32_t g_Whi[LMAX*15*8192];
__device__ uint32_t g_Wlo[LMAX*15*8192];
__device__ uint32_t g_Ghi[LMAX*4096];
__device__ uint32_t g_Glo[LMAX*4096];

__device__ __forceinline__ uint32_t smem_u32(const void* p){
    uint32_t a;
    asm("{ .reg .u64 t; cvta.to.shared.u64 t, %1; cvt.u32.u64 %0, t; }" : "=r"(a) : "l"(p));
    return a;
}
// fast shifted softplus: arg of log is in [1,2] -> MUFU LG2 path is accurate
__device__ __forceinline__ float sspf(float x){
    return fmaxf(x, 0.0f) + __logf(1.0f + __expf(-fabsf(x))) - 0.6931471805599453f;
}
__device__ __forceinline__ uint32_t bits2(__nv_bfloat162 v){
    return *reinterpret_cast<uint32_t*>(&v);
}

#define LDSM_X4(r0,r1,r2,r3,addr) \
    asm volatile("ldmatrix.sync.aligned.m8n8.x4.shared.b16 {%0,%1,%2,%3}, [%4];" \
        : "=r"(r0), "=r"(r1), "=r"(r2), "=r"(r3) : "r"(addr))

#define MMA16816(d, a0,a1,a2,a3, b0,b1) \
    asm volatile("mma.sync.aligned.m16n8k16.row.col.f32.bf16.bf16.f32 " \
        "{%0,%1,%2,%3}, {%4,%5,%6,%7}, {%8,%9}, {%0,%1,%2,%3};" \
        : "+f"((d)[0]), "+f"((d)[1]), "+f"((d)[2]), "+f"((d)[3]) \
        : "r"(a0), "r"(a1), "r"(a2), "r"(a3), "r"(b0), "r"(b1))

#define CP_ASYNC16(saddr, gptr) \
    asm volatile("cp.async.cg.shared.global [%0], [%1], 16;" :: "r"(saddr), "l"(gptr))
#define CP_COMMIT() asm volatile("cp.async.commit_group;" ::: "memory")
#define CP_WAIT0()  asm volatile("cp.async.wait_group 0;" ::: "memory")
#define CP_WAIT1()  asm volatile("cp.async.wait_group 1;" ::: "memory")

// ---------------- helper kernels (unchanged, validated) ----------------
__global__ void zero_kernel(float* __restrict__ p, int n){
    int i = blockIdx.x * blockDim.x + threadIdx.x;
    if (i < n) p[i] = 0.0f;
}

__global__ void scatter_kernel(const float* __restrict__ radial,
                               const int*   __restrict__ idx,
                               float* __restrict__ S, int P){
    int gid = blockIdx.x * blockDim.x + threadIdx.x;
    if (gid >= P * (RD/4)) return;
    int c = gid & 15;
    int p = gid >> 4;
    float4 v = *reinterpret_cast<const float4*>(radial + (size_t)p * RD + c * 4);
    int a0 = idx[p];
    int a1 = idx[P + p];
    atomicAdd(reinterpret_cast<float4*>(S + (size_t)a0 * RD + c * 4), v);
    atomicAdd(reinterpret_cast<float4*>(S + (size_t)a1 * RD + c * 4), v);
}

__global__ void __launch_bounds__(256) prep_weights(
    const float* __restrict__ W_J, const float* __restrict__ W_I,
    const float* __restrict__ W_int,
    const float* __restrict__ ri_W1, const float* __restrict__ ri_W2,
    const float* __restrict__ ra_W1, const float* __restrict__ ra_W2,
    const float* __restrict__ ro_W1, const float* __restrict__ ro_W2,
    const float* __restrict__ W_gate, int L)
{
    int b = blockIdx.x;
    if (b < L * 15){
        int l = b / 15, slot = b % 15;
        const float* W;
        size_t ff = (size_t)FD * FD;
        if      (slot == 0)  W = W_J   + (size_t)l * ff;
        else if (slot == 1)  W = W_I   + (size_t)l * ff;
        else if (slot == 2)  W = W_int + (size_t)l * ff;
        else if (slot <= 5)  W = ri_W1 + (size_t)(l*3 + (slot-3))  * ff;
        else if (slot <= 8)  W = ri_W2 + (size_t)(l*3 + (slot-6))  * ff;
        else if (slot <= 10) W = ra_W1 + (size_t)(l*2 + (slot-9))  * ff;
        else if (slot <= 12) W = ra_W2 + (size_t)(l*2 + (slot-11)) * ff;
        else if (slot == 13) W = ro_W1 + (size_t)l * ff;
        else                 W = ro_W2 + (size_t)l * ff;
        uint32_t* oh = g_Whi + (size_t)b * 8192;
        uint32_t* ol = g_Wlo + (size_t)b * 8192;
        for (int i = threadIdx.x; i < 8192; i += 256){
            int n  = i >> 6;
            int kk = i & 63;
            float a = W[(size_t)(2*kk)   * FD + n];
            float c = W[(size_t)(2*kk+1) * FD + n];
            __nv_bfloat162 h2 = __floats2bfloat162_rn(a, c);
            __nv_bfloat162 l2 = __floats2bfloat162_rn(a - __bfloat162float(h2.x),
                                                      c - __bfloat162float(h2.y));
            oh[i] = bits2(h2);
            ol[i] = bits2(l2);
        }
    } else {
        int l = b - L * 15;
        const float* W = W_gate + (size_t)l * RD * FD;   // [64, 128]
        uint32_t* oh = g_Ghi + (size_t)l * 4096;
        uint32_t* ol = g_Glo + (size_t)l * 4096;
        for (int i = threadIdx.x; i < 4096; i += 256){
            int n  = i >> 5;
            int kk = i & 31;
            float a = W[(size_t)(2*kk)   * FD + n];
            float c = W[(size_t)(2*kk+1) * FD + n];
            __nv_bfloat162 h2 = __floats2bfloat162_rn(a, c);
            __nv_bfloat162 l2 = __floats2bfloat162_rn(a - __bfloat162float(h2.x),
                                                      c - __bfloat162float(h2.y));
            oh[i] = bits2(h2);
            ol[i] = bits2(l2);
        }
    }
}

// ---------------- fused persistent network kernel ----------------
// 256 threads, 8 warps as 2(m) x 4(n), warp tile 32x32 (min LDSM redundancy)
// SMEM map (bytes):
//   A buf0 (hi, lo) : [0, 34816)        rows 64, stride 272, lo at +17408
//   A buf1 (hi, lo) : [34816, 69632)
//   S planes        : [69632, 88064)    rows 64, stride 144, lo at +9216
//   B buf0 (hi, lo) : [88064, 157696)   rows 128, stride 272, lo at +34816
//   B buf1 (hi, lo) : [157696, 227328)
//   rowsum          : [227328, 227584)
#define OFF_A0  0
#define OFF_A1  34816
#define A_LO    17408
#define OFF_S   69632
#define S_LO    9216
#define OFF_B0  88064
#define OFF_B1  157696
#define B_LO    34816
#define OFF_RS  227328
#define SM_TOT  227584

template<int KSTEPS>
__device__ __forceinline__ void mma_tile(
    uint32_t pAh, uint32_t pAl, uint32_t a0o, uint32_t a1o,
    uint32_t pBh, uint32_t pBl, uint32_t b0o, uint32_t b1o,
    float (&acc)[2][4][4])
{
    #pragma unroll
    for (int ks = 0; ks < KSTEPS; ks++){
        const uint32_t kb = ks * 32;
        uint32_t ah[2][4], al[2][4], bh[2][4], bl[2][4];
        LDSM_X4(ah[0][0],ah[0][1],ah[0][2],ah[0][3], pAh + a0o + kb);
        LDSM_X4(ah[1][0],ah[1][1],ah[1][2],ah[1][3], pAh + a1o + kb);
        LDSM_X4(bh[0][0],bh[0][1],bh[0][2],bh[0][3], pBh + b0o + kb);
        LDSM_X4(bh[1][0],bh[1][1],bh[1][2],bh[1][3], pBh + b1o + kb);
        LDSM_X4(al[0][0],al[0][1],al[0][2],al[0][3], pAl + a0o + kb);
        LDSM_X4(al[1][0],al[1][1],al[1][2],al[1][3], pAl + a1o + kb);
        LDSM_X4(bl[0][0],bl[0][1],bl[0][2],bl[0][3], pBl + b0o + kb);
        LDSM_X4(bl[1][0],bl[1][1],bl[1][2],bl[1][3], pBl + b1o + kb);
        #pragma unroll
        for (int mt = 0; mt < 2; mt++)
            #pragma unroll
            for (int nt = 0; nt < 4; nt++){
                const int np = nt >> 1, nq = (nt & 1) * 2;
                MMA16816(acc[mt][nt], ah[mt][0],ah[mt][1],ah[mt][2],ah[mt][3],
                         bh[np][nq], bh[np][nq+1]);
                MMA16816(acc[mt][nt], ah[mt][0],ah[mt][1],ah[mt][2],ah[mt][3],
                         bl[np][nq], bl[np][nq+1]);
                MMA16816(acc[mt][nt], al[mt][0],al[mt][1],al[mt][2],al[mt][3],
                         bh[np][nq], bh[np][nq+1]);
            }
    }
}

__device__ __forceinline__ void stage_w(int l, int slot,
    const uint32_t** hi, const uint32_t** lo, int* ch)
{
    if (slot == 2){
        *hi = g_Ghi + (size_t)l * 4096; *lo = g_Glo + (size_t)l * 4096; *ch = 8;
        return;
    }
    int ps;
    switch (slot){
        case 0:  ps = 0;  break;  case 1:  ps = 1;  break;
        case 3:  ps = 3;  break;  case 5:  ps = 4;  break;  case 7:  ps = 5;  break;
        case 4:  ps = 6;  break;  case 6:  ps = 7;  break;  case 8:  ps = 8;  break;
        case 9:  ps = 2;  break;
        case 10: ps = 9;  break;  case 12: ps = 10; break;
        case 11: ps = 11; break;  case 13: ps = 12; break;
        case 14: ps = 13; break;  default: ps = 14; break;
    }
    size_t o = (size_t)(l * 15 + ps) * 8192;
    *hi = g_Whi + o; *lo = g_Wlo + o; *ch = 16;
}

__global__ void __launch_bounds__(256, 1) fused_net(
    const float* __restrict__ features,
    const float* __restrict__ b_I,  const float* __restrict__ b_J,
    const float* __restrict__ gvec, const float* __restrict__ b_int,
    const float* __restrict__ ri_b1, const float* __restrict__ ri_b2,
    const float* __restrict__ ra_b1, const float* __restrict__ ra_b2,
    const float* __restrict__ ro_b1, const float* __restrict__ ro_b2,
    const float* __restrict__ W_out, const float* __restrict__ b_out,
    float* __restrict__ E, float* __restrict__ outFeat, int L)
{
    extern __shared__ char smem[];
    const uint32_t sb = smem_u32(smem);
    float* rowsum = reinterpret_cast<float*>(smem + OFF_RS);

    const int tid = threadIdx.x, wid = tid >> 5, lane = tid & 31;
    const int wm = wid >> 2, wn = wid & 3;      // 2 x 4 warp grid
    const int mat = lane >> 3, r = lane & 7;
    const int g = lane >> 2, c2 = (lane & 3) * 2;
    const int colbase = wn * 32 + c2;           // + nt*8, nt in 0..3
    const int rowbase = wm * 32 + g;            // + mt*16 + hh*8 (local)
    const int grow0 = blockIdx.x * 64;

    // ldmatrix lane offsets
    uint32_t aoffA[2], aoffS[2];
    #pragma unroll
    for (int mt = 0; mt < 2; mt++){
        int rr = wm*32 + mt*16 + r + ((mat & 1) << 3);
        int kc = ((mat >> 1) << 3) * 2;
        aoffA[mt] = (uint32_t)(rr * 272 + kc);
        aoffS[mt] = (uint32_t)(rr * 144 + kc);
    }
    uint32_t boff[2];
    #pragma unroll
    for (int np = 0; np < 2; np++)
        boff[np] = (uint32_t)((wn*32 + np*16 + ((mat >> 1) << 3) + r) * 272
                              + ((mat & 1) << 3) * 2);

    // ---------------- init ----------------
    for (int i = tid; i < 64; i += 256) rowsum[i] = 0.f;

    // register activation buffers (fragment layout), 32 floats each
    float rF[2][4][4], rG[2][4][4], rH[2][4][4], rX[2][4][4];

    // load features -> rF; build A buf0 = split(ssp(rF))
    #pragma unroll
    for (int mt = 0; mt < 2; mt++)
        #pragma unroll
        for (int hh = 0; hh < 2; hh++){
            int row = rowbase + mt*16 + hh*8;
            #pragma unroll
            for (int nt = 0; nt < 4; nt++){
                float2 v = *reinterpret_cast<const float2*>(
                    features + (size_t)(grow0 + row) * FD + colbase + nt*8);
                rF[mt][nt][hh*2]   = v.x;
                rF[mt][nt][hh*2+1] = v.y;
                float s0 = sspf(v.x), s1 = sspf(v.y);
                __nv_bfloat162 h2 = __floats2bfloat162_rn(s0, s1);
                __nv_bfloat162 l2 = __floats2bfloat162_rn(s0 - __bfloat162float(h2.x),
                                                          s1 - __bfloat162float(h2.y));
                char* p = smem + OFF_A0 + row * 272 + (colbase + nt*8) * 2;
                *reinterpret_cast<uint32_t*>(p)        = bits2(h2);
                *reinterpret_cast<uint32_t*>(p + A_LO) = bits2(l2);
            }
        }

    // build S planes (once): S tile [64 x 64] fp32 -> bf16 hi/lo, stride 144
    for (int i = tid; i < 64 * 32; i += 256){
        int row = i >> 5, kk = i & 31;
        float2 v = *reinterpret_cast<const float2*>(
            g_S + (size_t)(grow0 + row) * RD + 2 * kk);
        __nv_bfloat162 h2 = __floats2bfloat162_rn(v.x, v.y);
        __nv_bfloat162 l2 = __floats2bfloat162_rn(v.x - __bfloat162float(h2.x),
                                                  v.y - __bfloat162float(h2.y));
        char* p = smem + OFF_S + row * 144 + kk * 4;
        *reinterpret_cast<uint32_t*>(p)        = bits2(h2);
        *reinterpret_cast<uint32_t*>(p + S_LO) = bits2(l2);
    }

    // prefetch stage 0 weights into buf0
    {
        const uint32_t *hi, *lo; int ch;
        stage_w(0, 0, &hi, &lo, &ch);
        uint32_t bBh = sb + OFF_B0, bBl = bBh + B_LO;
        for (int i = tid; i < 128 * ch; i += 256){
            int n = i / ch, c = i - n * ch;
            uint32_t d = (uint32_t)(n * 272 + c * 16);
            CP_ASYNC16(bBh + d, (const uint4*)hi + i);
            CP_ASYNC16(bBl + d, (const uint4*)lo + i);
        }
        CP_COMMIT();
    }

    int curA = 0;                              // A read buffer for current stage
    const int NS = 16 * L;
    for (int s = 0; s < NS; s++){
        const int l = s >> 4, slot = s & 15;

        // prefetch next stage weights into B buf (s+1)&1
        if (s + 1 < NS){
            const uint32_t *hi, *lo; int ch;
            stage_w((s+1) >> 4, (s+1) & 15, &hi, &lo, &ch);
            uint32_t base = sb + (((s+1) & 1) ? OFF_B1 : OFF_B0);
            uint32_t bBl2 = base + B_LO;
            for (int i = tid; i < 128 * ch; i += 256){
                int n = i / ch, c = i - n * ch;
                uint32_t d = (uint32_t)(n * 272 + c * 16);
                CP_ASYNC16(base + d, (const uint4*)hi + i);
                CP_ASYNC16(bBl2 + d, (const uint4*)lo + i);
            }
            CP_COMMIT();
            CP_WAIT1();
        } else {
            CP_WAIT0();
        }

        // hoist per-stage column vectors (LDG latency hides under MMA)
        float2 bv[4] = {{0.f,0.f},{0.f,0.f},{0.f,0.f},{0.f,0.f}};
        float2 xv[4] = {{0.f,0.f},{0.f,0.f},{0.f,0.f},{0.f,0.f}};
        {
            const float* bias = nullptr;
            switch (slot){
                case 0:  bias = b_J   + (size_t)l * FD; break;
                case 1:  bias = b_I   + (size_t)l * FD; break;
                case 2:  break;
                case 3:  bias = ri_b1 + (size_t)(l*3 + 0) * FD; break;
                case 5:  bias = ri_b1 + (size_t)(l*3 + 1) * FD; break;
                case 7:  bias = ri_b1 + (size_t)(l*3 + 2) * FD; break;
                case 4:  bias = ri_b2 + (size_t)(l*3 + 0) * FD; break;
                case 6:  bias = ri_b2 + (size_t)(l*3 + 1) * FD; break;
                case 8:  bias = ri_b2 + (size_t)(l*3 + 2) * FD; break;
                case 9:  bias = b_int + (size_t)l * FD; break;
                case 10: bias = ra_b1 + (size_t)(l*2 + 0) * FD; break;
                case 12: bias = ra_b1 + (size_t)(l*2 + 1) * FD; break;
                case 11: bias = ra_b2 + (size_t)(l*2 + 0) * FD; break;
                case 13: bias = ra_b2 + (size_t)(l*2 + 1) * FD; break;
                case 14: bias = ro_b1 + (size_t)l * FD; break;
                default: bias = ro_b2 + (size_t)l * FD; break;
            }
            if (bias){
                #pragma unroll
                for (int nt = 0; nt < 4; nt++)
                    bv[nt] = *reinterpret_cast<const float2*>(bias + colbase + nt*8);
            }
            if (slot == 9){
                const float* gv = gvec + (size_t)l * FD;
                #pragma unroll
                for (int nt = 0; nt < 4; nt++)
                    xv[nt] = *reinterpret_cast<const float2*>(gv + colbase + nt*8);
            } else if (slot == 15){
                const float* wo = W_out + (size_t)l * FD;
                #pragma unroll
                for (int nt = 0; nt < 4; nt++)
                    xv[nt] = *reinterpret_cast<const float2*>(wo + colbase + nt*8);
            }
        }

        __syncthreads();   // B[s] arrived everywhere + prev epilogue STS visible

        // ---- mainloop ----
        float acc[2][4][4];
        #pragma unroll
        for (int i = 0; i < 2; i++)
            #pragma unroll
            for (int j = 0; j < 4; j++)
                #pragma unroll
                for (int q = 0; q < 4; q++) acc[i][j][q] = 0.f;

        uint32_t bB = sb + ((s & 1) ? OFF_B1 : OFF_B0);
        uint32_t aBase = sb + (curA ? OFF_A1 : OFF_A0);
        if (slot == 2)
            mma_tile<4>(sb + OFF_S, sb + OFF_S + S_LO, aoffS[0], aoffS[1],
                        bB, bB + B_LO, boff[0], boff[1], acc);
        else
            mma_tile<8>(aBase, aBase + A_LO, aoffA[0], aoffA[1],
                        bB, bB + B_LO, boff[0], boff[1], acc);

        // ---- epilogue (no barrier: writes go to the OTHER A buffer) ----
        #pragma unroll
        for (int nt = 0; nt < 4; nt++)
            #pragma unroll
            for (int mt = 0; mt < 2; mt++){
                acc[mt][nt][0] += bv[nt].x; acc[mt][nt][1] += bv[nt].y;
                acc[mt][nt][2] += bv[nt].x; acc[mt][nt][3] += bv[nt].y;
            }

        bool writeA = true;
        float (*src)[4][4] = acc;

        if (slot == 0){
            #pragma unroll
            for (int mt = 0; mt < 2; mt++)
                #pragma unroll
                for (int nt = 0; nt < 4; nt++)
                    #pragma unroll
                    for (int q = 0; q < 4; q++) rG[mt][nt][q] = sspf(acc[mt][nt][q]);
            writeA = false;
        } else if (slot == 1){
            #pragma unroll
            for (int mt = 0; mt < 2; mt++)
                #pragma unroll
                for (int nt = 0; nt < 4; nt++)
                    #pragma unroll
                    for (int q = 0; q < 4; q++) rH[mt][nt][q] = sspf(acc[mt][nt][q]);
            writeA = false;
        } else if (slot == 2){
            #pragma unroll
            for (int mt = 0; mt < 2; mt++)
                #pragma unroll
                for (int nt = 0; nt < 4; nt++)
                    #pragma unroll
                    for (int q = 0; q < 4; q++)
                        rX[mt][nt][q] = acc[mt][nt][q] * rG[mt][nt][q] + rH[mt][nt][q];
            src = rX;
        } else if (slot == 4 || slot == 6 || slot == 8){
            #pragma unroll
            for (int mt = 0; mt < 2; mt++)
                #pragma unroll
                for (int nt = 0; nt < 4; nt++)
                    #pragma unroll
                    for (int q = 0; q < 4; q++) rX[mt][nt][q] += acc[mt][nt][q];
            src = rX;
        } else if (slot == 9){
            #pragma unroll
            for (int nt = 0; nt < 4; nt++)
                #pragma unroll
                for (int mt = 0; mt < 2; mt++){
                    rF[mt][nt][0] = fmaf(rF[mt][nt][0], xv[nt].x, acc[mt][nt][0]);
                    rF[mt][nt][1] = fmaf(rF[mt][nt][1], xv[nt].y, acc[mt][nt][1]);
                    rF[mt][nt][2] = fmaf(rF[mt][nt][2], xv[nt].x, acc[mt][nt][2]);
                    rF[mt][nt][3] = fmaf(rF[mt][nt][3], xv[nt].y, acc[mt][nt][3]);
                }
            src = rF;
        } else if (slot == 11 || slot == 13){
            #pragma unroll
            for (int mt = 0; mt < 2; mt++)
                #pragma unroll
                for (int nt = 0; nt < 4; nt++)
                    #pragma unroll
                    for (int q = 0; q < 4; q++) rF[mt][nt][q] += acc[mt][nt][q];
            src = rF;
        } else if (slot == 15){
            float er[2][2] = {{0.f, 0.f}, {0.f, 0.f}};
            #pragma unroll
            for (int nt = 0; nt < 4; nt++){
                #pragma unroll
                for (int mt = 0; mt < 2; mt++)
                    #pragma unroll
                    for (int hh = 0; hh < 2; hh++){
                        float y0 = acc[mt][nt][hh*2]   + rF[mt][nt][hh*2];
                        float y1 = acc[mt][nt][hh*2+1] + rF[mt][nt][hh*2+1];
                        er[mt][hh] += sspf(y0) * xv[nt].x + sspf(y1) * xv[nt].y;
                    }
            }
            #pragma unroll
            for (int mt = 0; mt < 2; mt++)
                #pragma unroll
                for (int hh = 0; hh < 2; hh++){
                    float v = er[mt][hh];
                    v += __shfl_xor_sync(0xffffffff, v, 1);
                    v += __shfl_xor_sync(0xffffffff, v, 2);
                    if ((lane & 3) == 0)
                        atomicAdd(&rowsum[rowbase + mt*16 + hh*8], v);
                }
            src = rF;
        }
        // slots 3,5,7,10,12,14: src stays acc (t-stages)

        if (writeA){
            char* dst = smem + (curA ? OFF_A0 : OFF_A1);   // write the OTHER buffer
            #pragma unroll
            for (int mt = 0; mt < 2; mt++)
                #pragma unroll
                for (int hh = 0; hh < 2; hh++){
                    int row = rowbase + mt*16 + hh*8;
                    #pragma unroll
                    for (int nt = 0; nt < 4; nt++){
                        float s0 = sspf(src[mt][nt][hh*2]);
                        float s1 = sspf(src[mt][nt][hh*2+1]);
                        __nv_bfloat162 h2 = __floats2bfloat162_rn(s0, s1);
                        __nv_bfloat162 l2 = __floats2bfloat162_rn(
                            s0 - __bfloat162float(h2.x), s1 - __bfloat162float(h2.y));
                        char* p = dst + row * 272 + (colbase + nt*8) * 2;
                        *reinterpret_cast<uint32_t*>(p)        = bits2(h2);
                        *reinterpret_cast<uint32_t*>(p + A_LO) = bits2(l2);
                    }
                }
            curA ^= 1;
        }
    }

    __syncthreads();

    // energies
    if (tid < 64){
        float sb2 = 0.f;
        for (int l = 0; l < L; l++) sb2 += b_out[l];
        E[grow0 + tid] = rowsum[tid] + sb2;
    }
    // final features from rF
    #pragma unroll
    for (int mt = 0; mt < 2; mt++)
        #pragma unroll
        for (int hh = 0; hh < 2; hh++){
            int row = rowbase + mt*16 + hh*8;
            #pragma unroll
            for (int nt = 0; nt < 4; nt++){
                float2 v = make_float2(rF[mt][nt][hh*2], rF[mt][nt][hh*2+1]);
                *reinterpret_cast<float2*>(
                    outFeat + (size_t)(grow0 + row) * FD + colbase + nt*8) = v;
            }
        }
}

// ---------------- launch ----------------
extern "C" void kernel_launch(void* const* d_in, const int* in_sizes, int n_in,
                              void* d_out, int out_size)
{
    const float* features = (const float*)d_in[1];
    const float* radial   = (const float*)d_in[2];
    const int*   idx12    = (const int*)  d_in[3];
    const float* W_I   = (const float*)d_in[4];
    const float* b_I   = (const float*)d_in[5];
    const float* W_J   = (const float*)d_in[6];
    const float* b_J   = (const float*)d_in[7];
    const float* W_gate= (const float*)d_in[8];
    const float* gvec  = (const float*)d_in[9];
    const float* W_int = (const float*)d_in[10];
    const float* b_int = (const float*)d_in[11];
    const float* ri_b1 = (const float*)d_in[13];
    const float* ri_b2 = (const float*)d_in[15];
    const float* ra_b1 = (const float*)d_in[17];
    const float* ra_b2 = (const float*)d_in[19];
    const float* ro_b1 = (const float*)d_in[21];
    const float* ro_b2 = (const float*)d_in[23];
    const float* W_out = (const float*)d_in[24];
    const float* b_out = (const float*)d_in[25];

    const int P = in_sizes[3] / 2;
    const int N = in_sizes[1] / FD;
    const int L = in_sizes[4] / (FD * FD);

    float* S;
    cudaGetSymbolAddress((void**)&S, g_S);

    float* E = (float*)d_out;
    float* outFeat = (float*)d_out + N;

    cudaFuncSetAttribute(fused_net, cudaFuncAttributeMaxDynamicSharedMemorySize, SM_TOT);

    prep_weights<<<L * 15 + L, 256>>>(W_J, W_I, W_int,
        (const float*)d_in[12], (const float*)d_in[14],
        (const float*)d_in[16], (const float*)d_in[18],
        (const float*)d_in[20], (const float*)d_in[22], W_gate, L);
    zero_kernel<<<(N * RD + 255) / 256, 256>>>(S, N * RD);
    scatter_kernel<<<(P * (RD/4) + 255) / 256, 256>>>(radial, idx12, S, P);

    fused_net<<<N / 64, 256, SM_TOT>>>(features,
        b_I, b_J, gvec, b_int, ri_b1, ri_b2, ra_b1, ra_b2, ro_b1, ro_b2,
        W_out, b_out, E, outFeat, L);
}

// round 16
// speedup vs baseline: 1.1184x; 1.1184x over previous
#include <cuda_runtime.h>
#include <cuda_bf16.h>
#include <stdint.h>
#include <math.h>

#define FD 128
#define RD 64
#define NMAX 8192
#define LMAX 5

// ---------------- scratch (no runtime allocation allowed) ----------------
__device__ float g_S [NMAX*RD];
// pre-transposed/split weight images: B[n][k] packed as uint32 (2 bf16 along k)
__device__ uint32_t g_Whi[LMAX*15*8192];
__device__ uint32_t g_Wlo[LMAX*15*8192];
__device__ uint32_t g_Ghi[LMAX*4096];
__device__ uint32_t g_Glo[LMAX*4096];

__device__ __forceinline__ uint32_t smem_u32(const void* p){
    uint32_t a;
    asm("{ .reg .u64 t; cvta.to.shared.u64 t, %1; cvt.u32.u64 %0, t; }" : "=r"(a) : "l"(p));
    return a;
}
// fast shifted softplus: arg of log is in [1,2] -> MUFU LG2 path is accurate
__device__ __forceinline__ float sspf(float x){
    return fmaxf(x, 0.0f) + __logf(1.0f + __expf(-fabsf(x))) - 0.6931471805599453f;
}
__device__ __forceinline__ uint32_t bits2(__nv_bfloat162 v){
    return *reinterpret_cast<uint32_t*>(&v);
}

#define LDSM_X4(r0,r1,r2,r3,addr) \
    asm volatile("ldmatrix.sync.aligned.m8n8.x4.shared.b16 {%0,%1,%2,%3}, [%4];" \
        : "=r"(r0), "=r"(r1), "=r"(r2), "=r"(r3) : "r"(addr))

#define MMA16816(d, a0,a1,a2,a3, b0,b1) \
    asm volatile("mma.sync.aligned.m16n8k16.row.col.f32.bf16.bf16.f32 " \
        "{%0,%1,%2,%3}, {%4,%5,%6,%7}, {%8,%9}, {%0,%1,%2,%3};" \
        : "+f"((d)[0]), "+f"((d)[1]), "+f"((d)[2]), "+f"((d)[3]) \
        : "r"(a0), "r"(a1), "r"(a2), "r"(a3), "r"(b0), "r"(b1))

#define CP_ASYNC16(saddr, gptr) \
    asm volatile("cp.async.cg.shared.global [%0], [%1], 16;" :: "r"(saddr), "l"(gptr))
#define CP_COMMIT() asm volatile("cp.async.commit_group;" ::: "memory")
#define CP_WAIT0()  asm volatile("cp.async.wait_group 0;" ::: "memory")
#define CP_WAIT1()  asm volatile("cp.async.wait_group 1;" ::: "memory")

// ---------------- helper kernels (unchanged, validated) ----------------
__global__ void zero_kernel(float* __restrict__ p, int n){
    int i = blockIdx.x * blockDim.x + threadIdx.x;
    if (i < n) p[i] = 0.0f;
}

__global__ void scatter_kernel(const float* __restrict__ radial,
                               const int*   __restrict__ idx,
                               float* __restrict__ S, int P){
    int gid = blockIdx.x * blockDim.x + threadIdx.x;
    if (gid >= P * (RD/4)) return;
    int c = gid & 15;
    int p = gid >> 4;
    float4 v = *reinterpret_cast<const float4*>(radial + (size_t)p * RD + c * 4);
    int a0 = idx[p];
    int a1 = idx[P + p];
    atomicAdd(reinterpret_cast<float4*>(S + (size_t)a0 * RD + c * 4), v);
    atomicAdd(reinterpret_cast<float4*>(S + (size_t)a1 * RD + c * 4), v);
}

__global__ void __launch_bounds__(256) prep_weights(
    const float* __restrict__ W_J, const float* __restrict__ W_I,
    const float* __restrict__ W_int,
    const float* __restrict__ ri_W1, const float* __restrict__ ri_W2,
    const float* __restrict__ ra_W1, const float* __restrict__ ra_W2,
    const float* __restrict__ ro_W1, const float* __restrict__ ro_W2,
    const float* __restrict__ W_gate, int L)
{
    int b = blockIdx.x;
    if (b < L * 15){
        int l = b / 15, slot = b % 15;
        const float* W;
        size_t ff = (size_t)FD * FD;
        if      (slot == 0)  W = W_J   + (size_t)l * ff;
        else if (slot == 1)  W = W_I   + (size_t)l * ff;
        else if (slot == 2)  W = W_int + (size_t)l * ff;
        else if (slot <= 5)  W = ri_W1 + (size_t)(l*3 + (slot-3))  * ff;
        else if (slot <= 8)  W = ri_W2 + (size_t)(l*3 + (slot-6))  * ff;
        else if (slot <= 10) W = ra_W1 + (size_t)(l*2 + (slot-9))  * ff;
        else if (slot <= 12) W = ra_W2 + (size_t)(l*2 + (slot-11)) * ff;
        else if (slot == 13) W = ro_W1 + (size_t)l * ff;
        else                 W = ro_W2 + (size_t)l * ff;
        uint32_t* oh = g_Whi + (size_t)b * 8192;
        uint32_t* ol = g_Wlo + (size_t)b * 8192;
        for (int i = threadIdx.x; i < 8192; i += 256){
            int n  = i >> 6;
            int kk = i & 63;
            float a = W[(size_t)(2*kk)   * FD + n];
            float c = W[(size_t)(2*kk+1) * FD + n];
            __nv_bfloat162 h2 = __floats2bfloat162_rn(a, c);
            __nv_bfloat162 l2 = __floats2bfloat162_rn(a - __bfloat162float(h2.x),
                                                      c - __bfloat162float(h2.y));
            oh[i] = bits2(h2);
            ol[i] = bits2(l2);
        }
    } else {
        int l = b - L * 15;
        const float* W = W_gate + (size_t)l * RD * FD;   // [64, 128]
        uint32_t* oh = g_Ghi + (size_t)l * 4096;
        uint32_t* ol = g_Glo + (size_t)l * 4096;
        for (int i = threadIdx.x; i < 4096; i += 256){
            int n  = i >> 5;
            int kk = i & 31;
            float a = W[(size_t)(2*kk)   * FD + n];
            float c = W[(size_t)(2*kk+1) * FD + n];
            __nv_bfloat162 h2 = __floats2bfloat162_rn(a, c);
            __nv_bfloat162 l2 = __floats2bfloat162_rn(a - __bfloat162float(h2.x),
                                                      c - __bfloat162float(h2.y));
            oh[i] = bits2(h2);
            ol[i] = bits2(l2);
        }
    }
}

// ---------------- fused persistent network kernel ----------------
// 512 threads, 16 warps as 2(m) x 8(n), warp tile 32x16 (R13 geometry)
// SMEM map (bytes):
//   A buf0 (hi, lo) : [0, 34816)        rows 64, stride 272, lo at +17408
//   A buf1 (hi, lo) : [34816, 69632)
//   S planes        : [69632, 88064)    rows 64, stride 144, lo at +9216
//   B buf0 (hi, lo) : [88064, 157696)   rows 128, stride 272, lo at +34816
//   B buf1 (hi, lo) : [157696, 227328)
//   rowsum          : [227328, 227584)
#define OFF_A0  0
#define OFF_A1  34816
#define A_LO    17408
#define OFF_S   69632
#define S_LO    9216
#define OFF_B0  88064
#define OFF_B1  157696
#define B_LO    34816
#define OFF_RS  227328
#define SM_TOT  227584

template<int KSTEPS>
__device__ __forceinline__ void mma_tile(
    uint32_t pAh, uint32_t pAl, uint32_t a0o, uint32_t a1o,
    uint32_t pBh, uint32_t pBl, uint32_t bo, float (&acc)[2][2][4])
{
    #pragma unroll
    for (int ks = 0; ks < KSTEPS; ks++){
        const uint32_t kb = ks * 32;
        uint32_t ah[2][4], al[2][4], bh[4], bl[4];
        LDSM_X4(ah[0][0],ah[0][1],ah[0][2],ah[0][3], pAh + a0o + kb);
        LDSM_X4(ah[1][0],ah[1][1],ah[1][2],ah[1][3], pAh + a1o + kb);
        LDSM_X4(bh[0],bh[1],bh[2],bh[3], pBh + bo + kb);
        LDSM_X4(bl[0],bl[1],bl[2],bl[3], pBl + bo + kb);
        LDSM_X4(al[0][0],al[0][1],al[0][2],al[0][3], pAl + a0o + kb);
        LDSM_X4(al[1][0],al[1][1],al[1][2],al[1][3], pAl + a1o + kb);
        #pragma unroll
        for (int mt = 0; mt < 2; mt++)
            #pragma unroll
            for (int nt = 0; nt < 2; nt++){
                MMA16816(acc[mt][nt], ah[mt][0],ah[mt][1],ah[mt][2],ah[mt][3],
                         bh[nt*2], bh[nt*2+1]);
                MMA16816(acc[mt][nt], ah[mt][0],ah[mt][1],ah[mt][2],ah[mt][3],
                         bl[nt*2], bl[nt*2+1]);
                MMA16816(acc[mt][nt], al[mt][0],al[mt][1],al[mt][2],al[mt][3],
                         bh[nt*2], bh[nt*2+1]);
            }
    }
}

__device__ __forceinline__ void stage_w(int l, int slot,
    const uint32_t** hi, const uint32_t** lo, int* ch)
{
    if (slot == 2){
        *hi = g_Ghi + (size_t)l * 4096; *lo = g_Glo + (size_t)l * 4096; *ch = 8;
        return;
    }
    int ps;
    switch (slot){
        case 0:  ps = 0;  break;  case 1:  ps = 1;  break;
        case 3:  ps = 3;  break;  case 5:  ps = 4;  break;  case 7:  ps = 5;  break;
        case 4:  ps = 6;  break;  case 6:  ps = 7;  break;  case 8:  ps = 8;  break;
        case 9:  ps = 2;  break;
        case 10: ps = 9;  break;  case 12: ps = 10; break;
        case 11: ps = 11; break;  case 13: ps = 12; break;
        case 14: ps = 13; break;  default: ps = 14; break;
    }
    size_t o = (size_t)(l * 15 + ps) * 8192;
    *hi = g_Whi + o; *lo = g_Wlo + o; *ch = 16;
}

__global__ void __launch_bounds__(512, 1) fused_net(
    const float* __restrict__ features,
    const float* __restrict__ b_I,  const float* __restrict__ b_J,
    const float* __restrict__ gvec, const float* __restrict__ b_int,
    const float* __restrict__ ri_b1, const float* __restrict__ ri_b2,
    const float* __restrict__ ra_b1, const float* __restrict__ ra_b2,
    const float* __restrict__ ro_b1, const float* __restrict__ ro_b2,
    const float* __restrict__ W_out, const float* __restrict__ b_out,
    float* __restrict__ E, float* __restrict__ outFeat, int L)
{
    extern __shared__ char smem[];
    const uint32_t sb = smem_u32(smem);
    float* rowsum = reinterpret_cast<float*>(smem + OFF_RS);

    const int tid = threadIdx.x, wid = tid >> 5, lane = tid & 31;
    const int wm = wid >> 3, wn = wid & 7;
    const int mat = lane >> 3, r = lane & 7;
    const int g = lane >> 2, c2 = (lane & 3) * 2;
    const int colbase = wn * 16 + c2;          // + nt*8
    const int rowbase = wm * 32 + g;           // + mt*16 + hh*8 (local)
    const int grow0 = blockIdx.x * 64;

    // ldmatrix lane offsets
    uint32_t aoffA[2], aoffS[2];
    #pragma unroll
    for (int mt = 0; mt < 2; mt++){
        int rr = wm*32 + mt*16 + r + ((mat & 1) << 3);
        int kc = ((mat >> 1) << 3) * 2;
        aoffA[mt] = (uint32_t)(rr * 272 + kc);
        aoffS[mt] = (uint32_t)(rr * 144 + kc);
    }
    const uint32_t boff = (uint32_t)((wn*16 + ((mat >> 1) << 3) + r) * 272
                                     + ((mat & 1) << 3) * 2);

    // ---------------- init ----------------
    for (int i = tid; i < 64; i += 512) rowsum[i] = 0.f;

    // register activation buffers (fragment layout):
    // rF persistent; rA1 = rG then rX; rA2 = rH (dead after slot 2)
    float rF[2][2][4], rA1[2][2][4], rA2[2][2][4];

    // load features -> rF; build A buf0 = split(ssp(rF))
    #pragma unroll
    for (int mt = 0; mt < 2; mt++)
        #pragma unroll
        for (int hh = 0; hh < 2; hh++){
            int row = rowbase + mt*16 + hh*8;
            #pragma unroll
            for (int nt = 0; nt < 2; nt++){
                float2 v = *reinterpret_cast<const float2*>(
                    features + (size_t)(grow0 + row) * FD + colbase + nt*8);
                rF[mt][nt][hh*2]   = v.x;
                rF[mt][nt][hh*2+1] = v.y;
                float s0 = sspf(v.x), s1 = sspf(v.y);
                __nv_bfloat162 h2 = __floats2bfloat162_rn(s0, s1);
                __nv_bfloat162 l2 = __floats2bfloat162_rn(s0 - __bfloat162float(h2.x),
                                                          s1 - __bfloat162float(h2.y));
                char* p = smem + OFF_A0 + row * 272 + (colbase + nt*8) * 2;
                *reinterpret_cast<uint32_t*>(p)        = bits2(h2);
                *reinterpret_cast<uint32_t*>(p + A_LO) = bits2(l2);
            }
        }

    // build S planes (once): S tile [64 x 64] fp32 -> bf16 hi/lo, stride 144
    for (int i = tid; i < 64 * 32; i += 512){
        int row = i >> 5, kk = i & 31;
        float2 v = *reinterpret_cast<const float2*>(
            g_S + (size_t)(grow0 + row) * RD + 2 * kk);
        __nv_bfloat162 h2 = __floats2bfloat162_rn(v.x, v.y);
        __nv_bfloat162 l2 = __floats2bfloat162_rn(v.x - __bfloat162float(h2.x),
                                                  v.y - __bfloat162float(h2.y));
        char* p = smem + OFF_S + row * 144 + kk * 4;
        *reinterpret_cast<uint32_t*>(p)        = bits2(h2);
        *reinterpret_cast<uint32_t*>(p + S_LO) = bits2(l2);
    }

    // prefetch stage 0 weights into buf0
    {
        const uint32_t *hi, *lo; int ch;
        stage_w(0, 0, &hi, &lo, &ch);
        uint32_t bBh = sb + OFF_B0, bBl = bBh + B_LO;
        for (int i = tid; i < 128 * ch; i += 512){
            int n = i / ch, c = i - n * ch;
            uint32_t d = (uint32_t)(n * 272 + c * 16);
            CP_ASYNC16(bBh + d, (const uint4*)hi + i);
            CP_ASYNC16(bBl + d, (const uint4*)lo + i);
        }
        CP_COMMIT();
    }

    int curA = 0;                              // A read buffer for current stage
    const int NS = 16 * L;
    for (int s = 0; s < NS; s++){
        const int l = s >> 4, slot = s & 15;

        // hoist per-stage column vectors (LDG latency hides under barrier wait)
        float2 bv[2] = {{0.f,0.f},{0.f,0.f}};
        float2 xv[2] = {{0.f,0.f},{0.f,0.f}};   // gvec (slot 9) or W_out (slot 15)
        {
            const float* bias = nullptr;
            switch (slot){
                case 0:  bias = b_J   + (size_t)l * FD; break;
                case 1:  bias = b_I   + (size_t)l * FD; break;
                case 2:  break;
                case 3:  bias = ri_b1 + (size_t)(l*3 + 0) * FD; break;
                case 5:  bias = ri_b1 + (size_t)(l*3 + 1) * FD; break;
                case 7:  bias = ri_b1 + (size_t)(l*3 + 2) * FD; break;
                case 4:  bias = ri_b2 + (size_t)(l*3 + 0) * FD; break;
                case 6:  bias = ri_b2 + (size_t)(l*3 + 1) * FD; break;
                case 8:  bias = ri_b2 + (size_t)(l*3 + 2) * FD; break;
                case 9:  bias = b_int + (size_t)l * FD; break;
                case 10: bias = ra_b1 + (size_t)(l*2 + 0) * FD; break;
                case 12: bias = ra_b1 + (size_t)(l*2 + 1) * FD; break;
                case 11: bias = ra_b2 + (size_t)(l*2 + 0) * FD; break;
                case 13: bias = ra_b2 + (size_t)(l*2 + 1) * FD; break;
                case 14: bias = ro_b1 + (size_t)l * FD; break;
                default: bias = ro_b2 + (size_t)l * FD; break;
            }
            if (bias){
                bv[0] = *reinterpret_cast<const float2*>(bias + colbase);
                bv[1] = *reinterpret_cast<const float2*>(bias + colbase + 8);
            }
            if (slot == 9){
                const float* gv = gvec + (size_t)l * FD;
                xv[0] = *reinterpret_cast<const float2*>(gv + colbase);
                xv[1] = *reinterpret_cast<const float2*>(gv + colbase + 8);
            } else if (slot == 15){
                const float* wo = W_out + (size_t)l * FD;
                xv[0] = *reinterpret_cast<const float2*>(wo + colbase);
                xv[1] = *reinterpret_cast<const float2*>(wo + colbase + 8);
            }
        }

        // barrier FIRST: all warps done with stage s-1 (B[s-1] buffer free,
        // prev epilogue STS visible). Prefetch after it is race-free.
        __syncthreads();

        if (s + 1 < NS){
            const uint32_t *hi, *lo; int ch;
            stage_w((s+1) >> 4, (s+1) & 15, &hi, &lo, &ch);
            uint32_t base = sb + (((s+1) & 1) ? OFF_B1 : OFF_B0);
            uint32_t bBl2 = base + B_LO;
            for (int i = tid; i < 128 * ch; i += 512){
                int n = i / ch, c = i - n * ch;
                uint32_t d = (uint32_t)(n * 272 + c * 16);
                CP_ASYNC16(base + d, (const uint4*)hi + i);
                CP_ASYNC16(bBl2 + d, (const uint4*)lo + i);
            }
            CP_COMMIT();
            CP_WAIT1();      // ensures group for stage s complete
        } else {
            CP_WAIT0();
        }

        // ---- mainloop (acc initialized with bias -> no epilogue add) ----
        float acc[2][2][4];
        #pragma unroll
        for (int mt = 0; mt < 2; mt++)
            #pragma unroll
            for (int nt = 0; nt < 2; nt++){
                acc[mt][nt][0] = bv[nt].x; acc[mt][nt][1] = bv[nt].y;
                acc[mt][nt][2] = bv[nt].x; acc[mt][nt][3] = bv[nt].y;
            }

        uint32_t bB = sb + ((s & 1) ? OFF_B1 : OFF_B0);
        uint32_t aBase = sb + (curA ? OFF_A1 : OFF_A0);
        if (slot == 2)
            mma_tile<4>(sb + OFF_S, sb + OFF_S + S_LO, aoffS[0], aoffS[1],
                        bB, bB + B_LO, boff, acc);
        else
            mma_tile<8>(aBase, aBase + A_LO, aoffA[0], aoffA[1],
                        bB, bB + B_LO, boff, acc);

        // ---- epilogue (no barrier: writes go to the OTHER A buffer) ----
        bool writeA = true;
        float (*src)[2][4] = acc;

        if (slot == 0){
            #pragma unroll
            for (int mt = 0; mt < 2; mt++)
                #pragma unroll
                for (int nt = 0; nt < 2; nt++)
                    #pragma unroll
                    for (int q = 0; q < 4; q++) rA1[mt][nt][q] = sspf(acc[mt][nt][q]);
            writeA = false;
        } else if (slot == 1){
            #pragma unroll
            for (int mt = 0; mt < 2; mt++)
                #pragma unroll
                for (int nt = 0; nt < 2; nt++)
                    #pragma unroll
                    for (int q = 0; q < 4; q++) rA2[mt][nt][q] = sspf(acc[mt][nt][q]);
            writeA = false;
        } else if (slot == 2){
            // rA1 := gate*rA1(g) + rA2(h_self)   (becomes rX)
            #pragma unroll
            for (int mt = 0; mt < 2; mt++)
                #pragma unroll
                for (int nt = 0; nt < 2; nt++)
                    #pragma unroll
                    for (int q = 0; q < 4; q++)
                        rA1[mt][nt][q] = acc[mt][nt][q] * rA1[mt][nt][q] + rA2[mt][nt][q];
            src = rA1;
        } else if (slot == 4 || slot == 6 || slot == 8){
            #pragma unroll
            for (int mt = 0; mt < 2; mt++)
                #pragma unroll
                for (int nt = 0; nt < 2; nt++)
                    #pragma unroll
                    for (int q = 0; q < 4; q++) rA1[mt][nt][q] += acc[mt][nt][q];
            src = rA1;
        } else if (slot == 9){
            #pragma unroll
            for (int nt = 0; nt < 2; nt++)
                #pragma unroll
                for (int mt = 0; mt < 2; mt++){
                    rF[mt][nt][0] = fmaf(rF[mt][nt][0], xv[nt].x, acc[mt][nt][0]);
                    rF[mt][nt][1] = fmaf(rF[mt][nt][1], xv[nt].y, acc[mt][nt][1]);
                    rF[mt][nt][2] = fmaf(rF[mt][nt][2], xv[nt].x, acc[mt][nt][2]);
                    rF[mt][nt][3] = fmaf(rF[mt][nt][3], xv[nt].y, acc[mt][nt][3]);
                }
            src = rF;
        } else if (slot == 11 || slot == 13){
            #pragma unroll
            for (int mt = 0; mt < 2; mt++)
                #pragma unroll
                for (int nt = 0; nt < 2; nt++)
                    #pragma unroll
                    for (int q = 0; q < 4; q++) rF[mt][nt][q] += acc[mt][nt][q];
            src = rF;
        } else if (slot == 15){
            float er[2][2] = {{0.f, 0.f}, {0.f, 0.f}};
            #pragma unroll
            for (int nt = 0; nt < 2; nt++){
                #pragma unroll
                for (int mt = 0; mt < 2; mt++)
                    #pragma unroll
                    for (int hh = 0; hh < 2; hh++){
                        float y0 = acc[mt][nt][hh*2]   + rF[mt][nt][hh*2];
                        float y1 = acc[mt][nt][hh*2+1] + rF[mt][nt][hh*2+1];
                        er[mt][hh] += sspf(y0) * xv[nt].x + sspf(y1) * xv[nt].y;
                    }
            }
            #pragma unroll
            for (int mt = 0; mt < 2; mt++)
                #pragma unroll
                for (int hh = 0; hh < 2; hh++){
                    float v = er[mt][hh];
                    v += __shfl_xor_sync(0xffffffff, v, 1);
                    v += __shfl_xor_sync(0xffffffff, v, 2);
                    if ((lane & 3) == 0)
                        atomicAdd(&rowsum[rowbase + mt*16 + hh*8], v);
                }
            src = rF;
        }
        // slots 3,5,7,10,12,14: src stays acc (t-stages)

        if (writeA){
            char* dst = smem + (curA ? OFF_A0 : OFF_A1);   // write the OTHER buffer
            #pragma unroll
            for (int mt = 0; mt < 2; mt++)
                #pragma unroll
                for (int hh = 0; hh < 2; hh++){
                    int row = rowbase + mt*16 + hh*8;
                    #pragma unroll
                    for (int nt = 0; nt < 2; nt++){
                        float s0 = sspf(src[mt][nt][hh*2]);
                        float s1 = sspf(src[mt][nt][hh*2+1]);
                        __nv_bfloat162 h2 = __floats2bfloat162_rn(s0, s1);
                        __nv_bfloat162 l2 = __floats2bfloat162_rn(
                            s0 - __bfloat162float(h2.x), s1 - __bfloat162float(h2.y));
                        char* p = dst + row * 272 + (colbase + nt*8) * 2;
                        *reinterpret_cast<uint32_t*>(p)        = bits2(h2);
                        *reinterpret_cast<uint32_t*>(p + A_LO) = bits2(l2);
                    }
                }
            curA ^= 1;
        }
    }

    __syncthreads();

    // energies
    if (tid < 64){
        float sb2 = 0.f;
        for (int l = 0; l < L; l++) sb2 += b_out[l];
        E[grow0 + tid] = rowsum[tid] + sb2;
    }
    // final features from rF
    #pragma unroll
    for (int mt = 0; mt < 2; mt++)
        #pragma unroll
        for (int hh = 0; hh < 2; hh++){
            int row = rowbase + mt*16 + hh*8;
            #pragma unroll
            for (int nt = 0; nt < 2; nt++){
                float2 v = make_float2(rF[mt][nt][hh*2], rF[mt][nt][hh*2+1]);
                *reinterpret_cast<float2*>(
                    outFeat + (size_t)(grow0 + row) * FD + colbase + nt*8) = v;
            }
        }
}

// ---------------- launch ----------------
extern "C" void kernel_launch(void* const* d_in, const int* in_sizes, int n_in,
                              void* d_out, int out_size)
{
    const float* features = (const float*)d_in[1];
    const float* radial   = (const float*)d_in[2];
    const int*   idx12    = (const int*)  d_in[3];
    const float* W_I   = (const float*)d_in[4];
    const float* b_I   = (const float*)d_in[5];
    const float* W_J   = (const float*)d_in[6];
    const float* b_J   = (const float*)d_in[7];
    const float* W_gate= (const float*)d_in[8];
    const float* gvec  = (const float*)d_in[9];
    const float* W_int = (const float*)d_in[10];
    const float* b_int = (const float*)d_in[11];
    const float* ri_b1 = (const float*)d_in[13];
    const float* ri_b2 = (const float*)d_in[15];
    const float* ra_b1 = (const float*)d_in[17];
    const float* ra_b2 = (const float*)d_in[19];
    const float* ro_b1 = (const float*)d_in[21];
    const float* ro_b2 = (const float*)d_in[23];
    const float* W_out = (const float*)d_in[24];
    const float* b_out = (const float*)d_in[25];

    const int P = in_sizes[3] / 2;
    const int N = in_sizes[1] / FD;
    const int L = in_sizes[4] / (FD * FD);

    float* S;
    cudaGetSymbolAddress((void**)&S, g_S);

    float* E = (float*)d_out;
    float* outFeat = (float*)d_out + N;

    cudaFuncSetAttribute(fused_net, cudaFuncAttributeMaxDynamicSharedMemorySize, SM_TOT);

    prep_weights<<<L * 15 + L, 256>>>(W_J, W_I, W_int,
        (const float*)d_in[12], (const float*)d_in[14],
        (const float*)d_in[16], (const float*)d_in[18],
        (const float*)d_in[20], (const float*)d_in[22], W_gate, L);
    zero_kernel<<<(N * RD + 255) / 256, 256>>>(S, N * RD);
    scatter_kernel<<<(P * (RD/4) + 255) / 256, 256>>>(radial, idx12, S, P);

    fused_net<<<N / 64, 512, SM_TOT>>>(features,
        b_I, b_J, gvec, b_int, ri_b1, ri_b2, ra_b1, ra_b2, ro_b1, ro_b2,
        W_out, b_out, E, outFeat, L);
}

// round 17
// speedup vs baseline: 1.1265x; 1.0072x over previous
#include <cuda_runtime.h>
#include <cuda_bf16.h>
#include <stdint.h>
#include <math.h>

#define FD 128
#define RD 64
#define NMAX 8192
#define LMAX 5

// ---------------- scratch (no runtime allocation allowed) ----------------
__device__ float g_S [NMAX*RD];
// pre-transposed/split weight images: B[n][k] packed as uint32 (2 bf16 along k)
__device__ uint32_t g_Whi[LMAX*15*8192];
__device__ uint32_t g_Wlo[LMAX*15*8192];
__device__ uint32_t g_Ghi[LMAX*4096];
__device__ uint32_t g_Glo[LMAX*4096];

__device__ __forceinline__ uint32_t smem_u32(const void* p){
    uint32_t a;
    asm("{ .reg .u64 t; cvta.to.shared.u64 t, %1; cvt.u32.u64 %0, t; }" : "=r"(a) : "l"(p));
    return a;
}
// fast shifted softplus: arg of log is in [1,2] -> MUFU LG2 path is accurate
__device__ __forceinline__ float sspf(float x){
    return fmaxf(x, 0.0f) + __logf(1.0f + __expf(-fabsf(x))) - 0.6931471805599453f;
}
__device__ __forceinline__ uint32_t bits2(__nv_bfloat162 v){
    return *reinterpret_cast<uint32_t*>(&v);
}

#define LDSM_X4(r0,r1,r2,r3,addr) \
    asm volatile("ldmatrix.sync.aligned.m8n8.x4.shared.b16 {%0,%1,%2,%3}, [%4];" \
        : "=r"(r0), "=r"(r1), "=r"(r2), "=r"(r3) : "r"(addr))

#define MMA16816(d, a0,a1,a2,a3, b0,b1) \
    asm volatile("mma.sync.aligned.m16n8k16.row.col.f32.bf16.bf16.f32 " \
        "{%0,%1,%2,%3}, {%4,%5,%6,%7}, {%8,%9}, {%0,%1,%2,%3};" \
        : "+f"((d)[0]), "+f"((d)[1]), "+f"((d)[2]), "+f"((d)[3]) \
        : "r"(a0), "r"(a1), "r"(a2), "r"(a3), "r"(b0), "r"(b1))

#define CP_ASYNC16(saddr, gptr) \
    asm volatile("cp.async.cg.shared.global [%0], [%1], 16;" :: "r"(saddr), "l"(gptr))
#define CP_COMMIT() asm volatile("cp.async.commit_group;" ::: "memory")
#define CP_WAIT0()  asm volatile("cp.async.wait_group 0;" ::: "memory")
#define CP_WAIT1()  asm volatile("cp.async.wait_group 1;" ::: "memory")

// ---------------- helper kernels ----------------
__global__ void zero_kernel(float* __restrict__ p, int n){
    int i = blockIdx.x * blockDim.x + threadIdx.x;
    if (i < n) p[i] = 0.0f;
}

// 4 threads per pair; each handles 4 chunk-groups of 16B (64B contiguous per
// iteration across the 4 lanes). idx loaded once per thread (4x less traffic).
__global__ void scatter_kernel(const float* __restrict__ radial,
                               const int*   __restrict__ idx,
                               float* __restrict__ S, int P){
    int gid = blockIdx.x * blockDim.x + threadIdx.x;
    if (gid >= P * 4) return;
    int p = gid >> 2, q = gid & 3;
    int a0 = idx[p];
    int a1 = idx[P + p];
    const float4* r4 = reinterpret_cast<const float4*>(radial + (size_t)p * RD);
    float4* s0 = reinterpret_cast<float4*>(S + (size_t)a0 * RD);
    float4* s1 = reinterpret_cast<float4*>(S + (size_t)a1 * RD);
    #pragma unroll
    for (int i = 0; i < 4; i++){
        int c = i * 4 + q;
        float4 v = r4[c];
        atomicAdd(&s0[c], v);
        atomicAdd(&s1[c], v);
    }
}

// transpose + bf16 hi/lo split via smem tile: coalesced reads AND writes.
__global__ void __launch_bounds__(256) prep_weights(
    const float* __restrict__ W_J, const float* __restrict__ W_I,
    const float* __restrict__ W_int,
    const float* __restrict__ ri_W1, const float* __restrict__ ri_W2,
    const float* __restrict__ ra_W1, const float* __restrict__ ra_W2,
    const float* __restrict__ ro_W1, const float* __restrict__ ro_W2,
    const float* __restrict__ W_gate, int L)
{
    extern __shared__ float sw[];   // [K][129] padded
    int b = blockIdx.x;
    const float* W; uint32_t *oh, *ol; int K, sh;
    if (b < L * 15){
        int l = b / 15, slot = b % 15;
        size_t ff = (size_t)FD * FD;
        if      (slot == 0)  W = W_J   + (size_t)l * ff;
        else if (slot == 1)  W = W_I   + (size_t)l * ff;
        else if (slot == 2)  W = W_int + (size_t)l * ff;
        else if (slot <= 5)  W = ri_W1 + (size_t)(l*3 + (slot-3))  * ff;
        else if (slot <= 8)  W = ri_W2 + (size_t)(l*3 + (slot-6))  * ff;
        else if (slot <= 10) W = ra_W1 + (size_t)(l*2 + (slot-9))  * ff;
        else if (slot <= 12) W = ra_W2 + (size_t)(l*2 + (slot-11)) * ff;
        else if (slot == 13) W = ro_W1 + (size_t)l * ff;
        else                 W = ro_W2 + (size_t)l * ff;
        oh = g_Whi + (size_t)b * 8192;
        ol = g_Wlo + (size_t)b * 8192;
        K = 128; sh = 6;
    } else {
        int l = b - L * 15;
        W  = W_gate + (size_t)l * RD * FD;   // [64, 128]
        oh = g_Ghi + (size_t)l * 4096;
        ol = g_Glo + (size_t)l * 4096;
        K = 64; sh = 5;
    }
    // coalesced load into padded smem tile
    for (int i = threadIdx.x; i < K * 128; i += 256)
        sw[(i >> 7) * 129 + (i & 127)] = W[i];
    __syncthreads();
    // transposed read (2-way bank conflict max), coalesced image write
    int K2 = K >> 1;
    for (int i = threadIdx.x; i < K2 * 128; i += 256){
        int n  = i >> sh;
        int kk = i & (K2 - 1);
        float a = sw[(2*kk)   * 129 + n];
        float c = sw[(2*kk+1) * 129 + n];
        __nv_bfloat162 h2 = __floats2bfloat162_rn(a, c);
        __nv_bfloat162 l2 = __floats2bfloat162_rn(a - __bfloat162float(h2.x),
                                                  c - __bfloat162float(h2.y));
        oh[i] = bits2(h2);
        ol[i] = bits2(l2);
    }
}

// ---------------- fused persistent network kernel ----------------
// 512 threads, 16 warps as 2(m) x 8(n), warp tile 32x16
// SMEM map (bytes):
//   A buf0 (hi, lo) : [0, 34816)        rows 64, stride 272, lo at +17408
//   A buf1 (hi, lo) : [34816, 69632)
//   S planes        : [69632, 88064)    rows 64, stride 144, lo at +9216
//   B buf0 (hi, lo) : [88064, 157696)   rows 128, stride 272, lo at +34816
//   B buf1 (hi, lo) : [157696, 227328)
//   rowsum          : [227328, 227584)
#define OFF_A0  0
#define OFF_A1  34816
#define A_LO    17408
#define OFF_S   69632
#define S_LO    9216
#define OFF_B0  88064
#define OFF_B1  157696
#define B_LO    34816
#define OFF_RS  227328
#define SM_TOT  227584

// B-fragment lookahead: kstep k+1's B frags load while kstep k's MMAs issue.
template<int KSTEPS>
__device__ __forceinline__ void mma_tile(
    uint32_t pAh, uint32_t pAl, uint32_t a0o, uint32_t a1o,
    uint32_t pBh, uint32_t pBl, uint32_t bo, float (&acc)[2][2][4])
{
    uint32_t bh[2][4], bl[2][4];
    LDSM_X4(bh[0][0],bh[0][1],bh[0][2],bh[0][3], pBh + bo);
    LDSM_X4(bl[0][0],bl[0][1],bl[0][2],bl[0][3], pBl + bo);
    #pragma unroll
    for (int ks = 0; ks < KSTEPS; ks++){
        const int cur = ks & 1, nxt = cur ^ 1;
        if (ks + 1 < KSTEPS){
            const uint32_t kb2 = (ks + 1) * 32;
            LDSM_X4(bh[nxt][0],bh[nxt][1],bh[nxt][2],bh[nxt][3], pBh + bo + kb2);
            LDSM_X4(bl[nxt][0],bl[nxt][1],bl[nxt][2],bl[nxt][3], pBl + bo + kb2);
        }
        const uint32_t kb = ks * 32;
        uint32_t ah[2][4], al[2][4];
        LDSM_X4(ah[0][0],ah[0][1],ah[0][2],ah[0][3], pAh + a0o + kb);
        LDSM_X4(ah[1][0],ah[1][1],ah[1][2],ah[1][3], pAh + a1o + kb);
        LDSM_X4(al[0][0],al[0][1],al[0][2],al[0][3], pAl + a0o + kb);
        LDSM_X4(al[1][0],al[1][1],al[1][2],al[1][3], pAl + a1o + kb);
        #pragma unroll
        for (int mt = 0; mt < 2; mt++)
            #pragma unroll
            for (int nt = 0; nt < 2; nt++){
                MMA16816(acc[mt][nt], ah[mt][0],ah[mt][1],ah[mt][2],ah[mt][3],
                         bh[cur][nt*2], bh[cur][nt*2+1]);
                MMA16816(acc[mt][nt], ah[mt][0],ah[mt][1],ah[mt][2],ah[mt][3],
                         bl[cur][nt*2], bl[cur][nt*2+1]);
                MMA16816(acc[mt][nt], al[mt][0],al[mt][1],al[mt][2],al[mt][3],
                         bh[cur][nt*2], bh[cur][nt*2+1]);
            }
    }
}

__device__ __forceinline__ void stage_w(int l, int slot,
    const uint32_t** hi, const uint32_t** lo, int* ch)
{
    if (slot == 2){
        *hi = g_Ghi + (size_t)l * 4096; *lo = g_Glo + (size_t)l * 4096; *ch = 8;
        return;
    }
    int ps;
    switch (slot){
        case 0:  ps = 0;  break;  case 1:  ps = 1;  break;
        case 3:  ps = 3;  break;  case 5:  ps = 4;  break;  case 7:  ps = 5;  break;
        case 4:  ps = 6;  break;  case 6:  ps = 7;  break;  case 8:  ps = 8;  break;
        case 9:  ps = 2;  break;
        case 10: ps = 9;  break;  case 12: ps = 10; break;
        case 11: ps = 11; break;  case 13: ps = 12; break;
        case 14: ps = 13; break;  default: ps = 14; break;
    }
    size_t o = (size_t)(l * 15 + ps) * 8192;
    *hi = g_Whi + o; *lo = g_Wlo + o; *ch = 16;
}

__global__ void __launch_bounds__(512, 1) fused_net(
    const float* __restrict__ features,
    const float* __restrict__ b_I,  const float* __restrict__ b_J,
    const float* __restrict__ gvec, const float* __restrict__ b_int,
    const float* __restrict__ ri_b1, const float* __restrict__ ri_b2,
    const float* __restrict__ ra_b1, const float* __restrict__ ra_b2,
    const float* __restrict__ ro_b1, const float* __restrict__ ro_b2,
    const float* __restrict__ W_out, const float* __restrict__ b_out,
    float* __restrict__ E, float* __restrict__ outFeat, int L)
{
    extern __shared__ char smem[];
    const uint32_t sb = smem_u32(smem);
    float* rowsum = reinterpret_cast<float*>(smem + OFF_RS);

    const int tid = threadIdx.x, wid = tid >> 5, lane = tid & 31;
    const int wm = wid >> 3, wn = wid & 7;
    const int mat = lane >> 3, r = lane & 7;
    const int g = lane >> 2, c2 = (lane & 3) * 2;
    const int colbase = wn * 16 + c2;          // + nt*8
    const int rowbase = wm * 32 + g;           // + mt*16 + hh*8 (local)
    const int grow0 = blockIdx.x * 64;

    // ldmatrix lane offsets
    uint32_t aoffA[2], aoffS[2];
    #pragma unroll
    for (int mt = 0; mt < 2; mt++){
        int rr = wm*32 + mt*16 + r + ((mat & 1) << 3);
        int kc = ((mat >> 1) << 3) * 2;
        aoffA[mt] = (uint32_t)(rr * 272 + kc);
        aoffS[mt] = (uint32_t)(rr * 144 + kc);
    }
    const uint32_t boff = (uint32_t)((wn*16 + ((mat >> 1) << 3) + r) * 272
                                     + ((mat & 1) << 3) * 2);

    // ---------------- init ----------------
    for (int i = tid; i < 64; i += 512) rowsum[i] = 0.f;

    // register activation buffers (fragment layout):
    // rF persistent; rA1 = rG then rX; rA2 = rH (dead after slot 2)
    float rF[2][2][4], rA1[2][2][4], rA2[2][2][4];

    // load features -> rF; build A buf0 = split(ssp(rF))
    #pragma unroll
    for (int mt = 0; mt < 2; mt++)
        #pragma unroll
        for (int hh = 0; hh < 2; hh++){
            int row = rowbase + mt*16 + hh*8;
            #pragma unroll
            for (int nt = 0; nt < 2; nt++){
                float2 v = *reinterpret_cast<const float2*>(
                    features + (size_t)(grow0 + row) * FD + colbase + nt*8);
                rF[mt][nt][hh*2]   = v.x;
                rF[mt][nt][hh*2+1] = v.y;
                float s0 = sspf(v.x), s1 = sspf(v.y);
                __nv_bfloat162 h2 = __floats2bfloat162_rn(s0, s1);
                __nv_bfloat162 l2 = __floats2bfloat162_rn(s0 - __bfloat162float(h2.x),
                                                          s1 - __bfloat162float(h2.y));
                char* p = smem + OFF_A0 + row * 272 + (colbase + nt*8) * 2;
                *reinterpret_cast<uint32_t*>(p)        = bits2(h2);
                *reinterpret_cast<uint32_t*>(p + A_LO) = bits2(l2);
            }
        }

    // build S planes (once): S tile [64 x 64] fp32 -> bf16 hi/lo, stride 144
    for (int i = tid; i < 64 * 32; i += 512){
        int row = i >> 5, kk = i & 31;
        float2 v = *reinterpret_cast<const float2*>(
            g_S + (size_t)(grow0 + row) * RD + 2 * kk);
        __nv_bfloat162 h2 = __floats2bfloat162_rn(v.x, v.y);
        __nv_bfloat162 l2 = __floats2bfloat162_rn(v.x - __bfloat162float(h2.x),
                                                  v.y - __bfloat162float(h2.y));
        char* p = smem + OFF_S + row * 144 + kk * 4;
        *reinterpret_cast<uint32_t*>(p)        = bits2(h2);
        *reinterpret_cast<uint32_t*>(p + S_LO) = bits2(l2);
    }

    // prefetch stage 0 weights into buf0
    {
        const uint32_t *hi, *lo; int ch;
        stage_w(0, 0, &hi, &lo, &ch);
        uint32_t bBh = sb + OFF_B0, bBl = bBh + B_LO;
        for (int i = tid; i < 128 * ch; i += 512){
            int n = i / ch, c = i - n * ch;
            uint32_t d = (uint32_t)(n * 272 + c * 16);
            CP_ASYNC16(bBh + d, (const uint4*)hi + i);
            CP_ASYNC16(bBl + d, (const uint4*)lo + i);
        }
        CP_COMMIT();
    }

    int curA = 0;                              // A read buffer for current stage
    const int NS = 16 * L;
    for (int s = 0; s < NS; s++){
        const int l = s >> 4, slot = s & 15;

        // hoist per-stage column vectors (LDG latency hides under barrier wait)
        float2 bv[2] = {{0.f,0.f},{0.f,0.f}};
        float2 xv[2] = {{0.f,0.f},{0.f,0.f}};   // gvec (slot 9) or W_out (slot 15)
        {
            const float* bias = nullptr;
            switch (slot){
                case 0:  bias = b_J   + (size_t)l * FD; break;
                case 1:  bias = b_I   + (size_t)l * FD; break;
                case 2:  break;
                case 3:  bias = ri_b1 + (size_t)(l*3 + 0) * FD; break;
                case 5:  bias = ri_b1 + (size_t)(l*3 + 1) * FD; break;
                case 7:  bias = ri_b1 + (size_t)(l*3 + 2) * FD; break;
                case 4:  bias = ri_b2 + (size_t)(l*3 + 0) * FD; break;
                case 6:  bias = ri_b2 + (size_t)(l*3 + 1) * FD; break;
                case 8:  bias = ri_b2 + (size_t)(l*3 + 2) * FD; break;
                case 9:  bias = b_int + (size_t)l * FD; break;
                case 10: bias = ra_b1 + (size_t)(l*2 + 0) * FD; break;
                case 12: bias = ra_b1 + (size_t)(l*2 + 1) * FD; break;
                case 11: bias = ra_b2 + (size_t)(l*2 + 0) * FD; break;
                case 13: bias = ra_b2 + (size_t)(l*2 + 1) * FD; break;
                case 14: bias = ro_b1 + (size_t)l * FD; break;
                default: bias = ro_b2 + (size_t)l * FD; break;
            }
            if (bias){
                bv[0] = *reinterpret_cast<const float2*>(bias + colbase);
                bv[1] = *reinterpret_cast<const float2*>(bias + colbase + 8);
            }
            if (slot == 9){
                const float* gv = gvec + (size_t)l * FD;
                xv[0] = *reinterpret_cast<const float2*>(gv + colbase);
                xv[1] = *reinterpret_cast<const float2*>(gv + colbase + 8);
            } else if (slot == 15){
                const float* wo = W_out + (size_t)l * FD;
                xv[0] = *reinterpret_cast<const float2*>(wo + colbase);
                xv[1] = *reinterpret_cast<const float2*>(wo + colbase + 8);
            }
        }

        // barrier FIRST: all warps done with stage s-1 (B[s-1] buffer free,
        // prev epilogue STS visible). Prefetch after it is race-free.
        __syncthreads();

        if (s + 1 < NS){
            const uint32_t *hi, *lo; int ch;
            stage_w((s+1) >> 4, (s+1) & 15, &hi, &lo, &ch);
            uint32_t base = sb + (((s+1) & 1) ? OFF_B1 : OFF_B0);
            uint32_t bBl2 = base + B_LO;
            for (int i = tid; i < 128 * ch; i += 512){
                int n = i / ch, c = i - n * ch;
                uint32_t d = (uint32_t)(n * 272 + c * 16);
                CP_ASYNC16(base + d, (const uint4*)hi + i);
                CP_ASYNC16(bBl2 + d, (const uint4*)lo + i);
            }
            CP_COMMIT();
            CP_WAIT1();      // ensures group for stage s complete
        } else {
            CP_WAIT0();
        }

        // ---- mainloop (acc initialized with bias -> no epilogue add) ----
        float acc[2][2][4];
        #pragma unroll
        for (int mt = 0; mt < 2; mt++)
            #pragma unroll
            for (int nt = 0; nt < 2; nt++){
                acc[mt][nt][0] = bv[nt].x; acc[mt][nt][1] = bv[nt].y;
                acc[mt][nt][2] = bv[nt].x; acc[mt][nt][3] = bv[nt].y;
            }

        uint32_t bB = sb + ((s & 1) ? OFF_B1 : OFF_B0);
        uint32_t aBase = sb + (curA ? OFF_A1 : OFF_A0);
        if (slot == 2)
            mma_tile<4>(sb + OFF_S, sb + OFF_S + S_LO, aoffS[0], aoffS[1],
                        bB, bB + B_LO, boff, acc);
        else
            mma_tile<8>(aBase, aBase + A_LO, aoffA[0], aoffA[1],
                        bB, bB + B_LO, boff, acc);

        // ---- epilogue (no barrier: writes go to the OTHER A buffer) ----
        bool writeA = true;
        float (*src)[2][4] = acc;

        if (slot == 0){
            #pragma unroll
            for (int mt = 0; mt < 2; mt++)
                #pragma unroll
                for (int nt = 0; nt < 2; nt++)
                    #pragma unroll
                    for (int q = 0; q < 4; q++) rA1[mt][nt][q] = sspf(acc[mt][nt][q]);
            writeA = false;
        } else if (slot == 1){
            #pragma unroll
            for (int mt = 0; mt < 2; mt++)
                #pragma unroll
                for (int nt = 0; nt < 2; nt++)
                    #pragma unroll
                    for (int q = 0; q < 4; q++) rA2[mt][nt][q] = sspf(acc[mt][nt][q]);
            writeA = false;
        } else if (slot == 2){
            // rA1 := gate*rA1(g) + rA2(h_self)   (becomes rX)
            #pragma unroll
            for (int mt = 0; mt < 2; mt++)
                #pragma unroll
                for (int nt = 0; nt < 2; nt++)
                    #pragma unroll
                    for (int q = 0; q < 4; q++)
                        rA1[mt][nt][q] = acc[mt][nt][q] * rA1[mt][nt][q] + rA2[mt][nt][q];
            src = rA1;
        } else if (slot == 4 || slot == 6 || slot == 8){
            #pragma unroll
            for (int mt = 0; mt < 2; mt++)
                #pragma unroll
                for (int nt = 0; nt < 2; nt++)
                    #pragma unroll
                    for (int q = 0; q < 4; q++) rA1[mt][nt][q] += acc[mt][nt][q];
            src = rA1;
        } else if (slot == 9){
            #pragma unroll
            for (int nt = 0; nt < 2; nt++)
                #pragma unroll
                for (int mt = 0; mt < 2; mt++){
                    rF[mt][nt][0] = fmaf(rF[mt][nt][0], xv[nt].x, acc[mt][nt][0]);
                    rF[mt][nt][1] = fmaf(rF[mt][nt][1], xv[nt].y, acc[mt][nt][1]);
                    rF[mt][nt][2] = fmaf(rF[mt][nt][2], xv[nt].x, acc[mt][nt][2]);
                    rF[mt][nt][3] = fmaf(rF[mt][nt][3], xv[nt].y, acc[mt][nt][3]);
                }
            src = rF;
        } else if (slot == 11 || slot == 13){
            #pragma unroll
            for (int mt = 0; mt < 2; mt++)
                #pragma unroll
                for (int nt = 0; nt < 2; nt++)
                    #pragma unroll
                    for (int q = 0; q < 4; q++) rF[mt][nt][q] += acc[mt][nt][q];
            src = rF;
        } else if (slot == 15){
            float er[2][2] = {{0.f, 0.f}, {0.f, 0.f}};
            #pragma unroll
            for (int nt = 0; nt < 2; nt++){
                #pragma unroll
                for (int mt = 0; mt < 2; mt++)
                    #pragma unroll
                    for (int hh = 0; hh < 2; hh++){
                        float y0 = acc[mt][nt][hh*2]   + rF[mt][nt][hh*2];
                        float y1 = acc[mt][nt][hh*2+1] + rF[mt][nt][hh*2+1];
                        er[mt][hh] += sspf(y0) * xv[nt].x + sspf(y1) * xv[nt].y;
                    }
            }
            #pragma unroll
            for (int mt = 0; mt < 2; mt++)
                #pragma unroll
                for (int hh = 0; hh < 2; hh++){
                    float v = er[mt][hh];
                    v += __shfl_xor_sync(0xffffffff, v, 1);
                    v += __shfl_xor_sync(0xffffffff, v, 2);
                    if ((lane & 3) == 0)
                        atomicAdd(&rowsum[rowbase + mt*16 + hh*8], v);
                }
            src = rF;
        }
        // slots 3,5,7,10,12,14: src stays acc (t-stages)

        if (writeA){
            char* dst = smem + (curA ? OFF_A0 : OFF_A1);   // write the OTHER buffer
            #pragma unroll
            for (int mt = 0; mt < 2; mt++)
                #pragma unroll
                for (int hh = 0; hh < 2; hh++){
                    int row = rowbase + mt*16 + hh*8;
                    #pragma unroll
                    for (int nt = 0; nt < 2; nt++){
                        float s0 = sspf(src[mt][nt][hh*2]);
                        float s1 = sspf(src[mt][nt][hh*2+1]);
                        __nv_bfloat162 h2 = __floats2bfloat162_rn(s0, s1);
                        __nv_bfloat162 l2 = __floats2bfloat162_rn(
                            s0 - __bfloat162float(h2.x), s1 - __bfloat162float(h2.y));
                        char* p = dst + row * 272 + (colbase + nt*8) * 2;
                        *reinterpret_cast<uint32_t*>(p)        = bits2(h2);
                        *reinterpret_cast<uint32_t*>(p + A_LO) = bits2(l2);
                    }
                }
            curA ^= 1;
        }
    }

    __syncthreads();

    // energies
    if (tid < 64){
        float sb2 = 0.f;
        for (int l = 0; l < L; l++) sb2 += b_out[l];
        E[grow0 + tid] = rowsum[tid] + sb2;
    }
    // final features from rF
    #pragma unroll
    for (int mt = 0; mt < 2; mt++)
        #pragma unroll
        for (int hh = 0; hh < 2; hh++){
            int row = rowbase + mt*16 + hh*8;
            #pragma unroll
            for (int nt = 0; nt < 2; nt++){
                float2 v = make_float2(rF[mt][nt][hh*2], rF[mt][nt][hh*2+1]);
                *reinterpret_cast<float2*>(
                    outFeat + (size_t)(grow0 + row) * FD + colbase + nt*8) = v;
            }
        }
}

// ---------------- launch ----------------
extern "C" void kernel_launch(void* const* d_in, const int* in_sizes, int n_in,
                              void* d_out, int out_size)
{
    const float* features = (const float*)d_in[1];
    const float* radial   = (const float*)d_in[2];
    const int*   idx12    = (const int*)  d_in[3];
    const float* W_I   = (const float*)d_in[4];
    const float* b_I   = (const float*)d_in[5];
    const float* W_J   = (const float*)d_in[6];
    const float* b_J   = (const float*)d_in[7];
    const float* W_gate= (const float*)d_in[8];
    const float* gvec  = (const float*)d_in[9];
    const float* W_int = (const float*)d_in[10];
    const float* b_int = (const float*)d_in[11];
    const float* ri_b1 = (const float*)d_in[13];
    const float* ri_b2 = (const float*)d_in[15];
    const float* ra_b1 = (const float*)d_in[17];
    const float* ra_b2 = (const float*)d_in[19];
    const float* ro_b1 = (const float*)d_in[21];
    const float* ro_b2 = (const float*)d_in[23];
    const float* W_out = (const float*)d_in[24];
    const float* b_out = (const float*)d_in[25];

    const int P = in_sizes[3] / 2;
    const int N = in_sizes[1] / FD;
    const int L = in_sizes[4] / (FD * FD);

    float* S;
    cudaGetSymbolAddress((void**)&S, g_S);

    float* E = (float*)d_out;
    float* outFeat = (float*)d_out + N;

    const int prepSm = 128 * 129 * 4;   // 66048 B
    cudaFuncSetAttribute(fused_net, cudaFuncAttributeMaxDynamicSharedMemorySize, SM_TOT);
    cudaFuncSetAttribute(prep_weights, cudaFuncAttributeMaxDynamicSharedMemorySize, prepSm);

    prep_weights<<<L * 15 + L, 256, prepSm>>>(W_J, W_I, W_int,
        (const float*)d_in[12], (const float*)d_in[14],
        (const float*)d_in[16], (const float*)d_in[18],
        (const float*)d_in[20], (const float*)d_in[22], W_gate, L);
    zero_kernel<<<(N * RD + 255) / 256, 256>>>(S, N * RD);
    scatter_kernel<<<(P * 4 + 255) / 256, 256>>>(radial, idx12, S, P);

    fused_net<<<N / 64, 512, SM_TOT>>>(features,
        b_I, b_J, gvec, b_int, ri_b1, ri_b2, ra_b1, ra_b2, ro_b1, ro_b2,
        W_out, b_out, E, outFeat, L);
}